// round 16
// baseline (speedup 1.0000x reference)
#include <cuda_runtime.h>
#include <math.h>

#define D_FEAT 8192
#define T_RES  2048
#define ORDER  16
#define DTAU   0.08
#define REG    0.0001f
#define EPS_C  1e-15f

#define ROW_BLOCKS 512   // k_A: 4 rows/block, 2 warps per row
#define NW  256
#define NWC 512
#define RI_STRIDE4 (D_FEAT / 8)   // int4 per row of the int16 matrix (1024)

// ---------------- device scratch (no allocations allowed) ----------------
__device__ short g_Ri[T_RES * D_FEAT];        // int16 row-scaled R (32 MB)
__device__ float g_rs[T_RES];                 // dequant scale  = rowmax/32767
__device__ float g_s[ORDER * T_RES];          // s_j = R~ q_j
__device__ float g_sf[T_RES];                 // R~ f
__device__ float g_Q[ORDER * D_FEAT];         // Lanczos basis
__device__ float g_wf[D_FEAT];                // current unnormalized basis vector
__device__ float g_upart[4 * D_FEAT];         // t-quarter partials of u = R~^T s_j
__device__ float g_nrm2_part[128];            // ||wf||^2 partials
__device__ float g_cpart[ROW_BLOCKS * ORDER]; // per-row-block partials of c_k
__device__ float g_b[ORDER + 1];              // g_b[0]=||F||, g_b[j]=beta[j-1]
__device__ float g_alpha[ORDER];

// unpack one 32-bit word (2 shorts) and fma with 2 fp32 weights
__device__ __forceinline__ void dq2(float& acc, int w, float q0, float q1) {
    short lo = (short)(w & 0xffff), hi = (short)(w >> 16);
    acc = fmaf((float)lo, q0, acc);
    acc = fmaf((float)hi, q1, acc);
}

// ========= fused quantization prologue: rowmax + quantize (warp/row) =========
__global__ void k_quant(const float* __restrict__ R) {
    int tx = threadIdx.x, lane = tx & 31, w = tx >> 5;
    int r = blockIdx.x * 8 + w;
    const float4* R4 = (const float4*)(R + (size_t)r * D_FEAT);
    float m = 0.f;
    #pragma unroll 8
    for (int it = 0; it < 64; it++) {
        float4 v = R4[it * 32 + lane];
        m = fmaxf(m, fmaxf(fmaxf(fabsf(v.x), fabsf(v.y)), fmaxf(fabsf(v.z), fabsf(v.w))));
    }
    #pragma unroll
    for (int o = 16; o; o >>= 1) m = fmaxf(m, __shfl_xor_sync(0xffffffffu, m, o));
    m = fmaxf(m, 1e-30f);
    if (lane == 0) g_rs[r] = m / 32767.0f;
    float q = 32767.0f / m;

    short4* O4 = (short4*)(g_Ri + (size_t)r * D_FEAT);
    #pragma unroll 8
    for (int it = 0; it < 64; it++) {
        float4 v = R4[it * 32 + lane];     // L1/L2-hot re-read
        short4 o;
        o.x = (short)__float2int_rn(v.x * q);
        o.y = (short)__float2int_rn(v.y * q);
        o.z = (short)__float2int_rn(v.z * q);
        o.w = (short)__float2int_rn(v.w * q);
        O4[it * 32 + lane] = o;
    }
}

// ================= prologue row: sf = R~ f (warp per row) =================
__global__ void k_row_f(const float* __restrict__ f) {
    int tx = threadIdx.x, lane = tx & 31, w = tx >> 5;
    int r = blockIdx.x * 8 + w;
    const int4* Ri4 = (const int4*)(g_Ri + (size_t)r * D_FEAT);
    const float4* f4 = (const float4*)f;
    float a0 = 0.f, a1 = 0.f;
    #pragma unroll 8
    for (int it = 0; it < 32; it++) {
        int i = it * 32 + lane;
        int4 rv = __ldg(Ri4 + i);
        float4 qa = f4[2 * i], qb = f4[2 * i + 1];
        dq2(a0, rv.x, qa.x, qa.y);
        dq2(a1, rv.y, qa.z, qa.w);
        dq2(a0, rv.z, qb.x, qb.y);
        dq2(a1, rv.w, qb.z, qb.w);
    }
    float acc = a0 + a1;
    #pragma unroll
    for (int o = 16; o; o >>= 1) acc += __shfl_xor_sync(0xffffffffu, acc, o);
    if (lane == 0) g_sf[r] = acc * g_rs[r];
}

// ====== prologue col: F = R~^T sf + E f ; wf = F ; ||F||^2 partials ======
// 128 blocks x 512 thr, 64 cols/block, full t range.
__global__ void k_prologue_col(const float* __restrict__ f) {
    __shared__ float s_sm[T_RES];
    __shared__ float4 shA[NWC], shB[NWC];
    __shared__ float sh_r1[16], sh_r2[16];
    __shared__ float shE;
    int tx = threadIdx.x, lane = tx & 31, w = tx >> 5;
    const float4* f4 = (const float4*)f;

    // stage scaled sf; per-block redundant ||sf||^2 and ||f||^2
    float ssf = 0.f;
    for (int i = tx; i < T_RES; i += NWC) {
        float v = g_sf[i];
        s_sm[i] = v * g_rs[i];
        ssf = fmaf(v, v, ssf);
    }
    float ff = 0.f;
    for (int i = tx; i < D_FEAT / 4; i += NWC) {
        float4 v = f4[i];
        ff = fmaf(v.x, v.x, fmaf(v.y, v.y, fmaf(v.z, v.z, fmaf(v.w, v.w, ff))));
    }
    #pragma unroll
    for (int o = 16; o; o >>= 1) {
        ssf += __shfl_xor_sync(0xffffffffu, ssf, o);
        ff  += __shfl_xor_sync(0xffffffffu, ff, o);
    }
    if (lane == 0) { sh_r1[w] = ssf; sh_r2[w] = ff; }
    __syncthreads();
    if (tx == 0) {
        float a = 0.f, b = 0.f;
        #pragma unroll
        for (int i = 0; i < 16; i++) { a += sh_r1[i]; b += sh_r2[i]; }
        shE = -a / (b + EPS_C);
    }
    __syncthreads();

    // u[col] = sum_t R~[t][col] * sf'[t]  (64 cols per block)
    int g = tx & 7, s = tx >> 3;          // g: 8 int4 cols, s in [0,64)
    const int4* Ri4 = (const int4*)g_Ri;
    size_t cbase = (size_t)blockIdx.x * 8 + g;
    float a[8];
    #pragma unroll
    for (int k = 0; k < 8; k++) a[k] = 0.f;
    #pragma unroll 4
    for (int it = 0; it < 32; it++) {
        int t = it * 64 + s;
        float sv = s_sm[t];
        int4 rv = __ldg(Ri4 + (size_t)t * RI_STRIDE4 + cbase);
        dq2(a[0], rv.x, sv, 0.f); dq2(a[1], rv.x, 0.f, sv);
        dq2(a[2], rv.y, sv, 0.f); dq2(a[3], rv.y, 0.f, sv);
        dq2(a[4], rv.z, sv, 0.f); dq2(a[5], rv.z, 0.f, sv);
        dq2(a[6], rv.w, sv, 0.f); dq2(a[7], rv.w, 0.f, sv);
    }
    shA[tx] = make_float4(a[0], a[1], a[2], a[3]);
    shB[tx] = make_float4(a[4], a[5], a[6], a[7]);
    #pragma unroll
    for (int off = 256; off >= 8; off >>= 1) {
        __syncthreads();
        if (tx < off) {
            float4 x = shA[tx], y = shA[tx + off];
            x.x += y.x; x.y += y.y; x.z += y.z; x.w += y.w; shA[tx] = x;
            x = shB[tx]; y = shB[tx + off];
            x.x += y.x; x.y += y.y; x.z += y.z; x.w += y.w; shB[tx] = x;
        }
    }
    __syncthreads();

    float nrm = 0.f;
    if (tx < 8) {
        float4 ua = shA[tx], ub = shB[tx];
        int c0 = blockIdx.x * 64 + tx * 8;
        float uv[8] = {ua.x, ua.y, ua.z, ua.w, ub.x, ub.y, ub.z, ub.w};
        #pragma unroll
        for (int k = 0; k < 8; k++) {
            float F = fmaf(shE, f[c0 + k], uv[k]);
            g_wf[c0 + k] = F;
            nrm = fmaf(F, F, nrm);
        }
    }
    if (tx < 32) {
        #pragma unroll
        for (int o = 4; o; o >>= 1) nrm += __shfl_xor_sync(0xffu, nrm, o);
        if (tx == 0) g_nrm2_part[blockIdx.x] = nrm;
    }
}

// == k_A: b=||wf||; s_j = R~*(wf/b); c-partials (4 rows/block, 2 warps/row) ==
__global__ void k_A(int j, int npart) {
    __shared__ float sh_r[8];
    __shared__ float sh_invb;
    __shared__ float shp[8];
    int tx = threadIdx.x, lane = tx & 31, w = tx >> 5;

    float p = (tx < npart) ? g_nrm2_part[tx] : 0.f;
    #pragma unroll
    for (int o = 16; o; o >>= 1) p += __shfl_xor_sync(0xffffffffu, p, o);
    if (lane == 0) sh_r[w] = p;
    __syncthreads();
    if (tx == 0) {
        float n = 0.f;
        #pragma unroll
        for (int i = 0; i < 8; i++) n += sh_r[i];
        float b = sqrtf(n);
        if (blockIdx.x == 0) g_b[j] = b;
        sh_invb = 1.0f / fmaxf(b, 1e-30f);
    }
    __syncthreads();

    int r0 = blockIdx.x * 4;
    int row = r0 + (w >> 1), half = w & 1;
    const int4* Ri4 = (const int4*)(g_Ri + (size_t)row * D_FEAT) + half * 512;
    const float4* w4 = (const float4*)g_wf + half * 1024;
    float a0 = 0.f, a1 = 0.f;
    #pragma unroll 8
    for (int it = 0; it < 16; it++) {
        int i = it * 32 + lane;
        int4 rv = __ldg(Ri4 + i);
        float4 qa = w4[2 * i], qb = w4[2 * i + 1];
        dq2(a0, rv.x, qa.x, qa.y);
        dq2(a1, rv.y, qa.z, qa.w);
        dq2(a0, rv.z, qb.x, qb.y);
        dq2(a1, rv.w, qb.z, qb.w);
    }
    float acc = a0 + a1;
    #pragma unroll
    for (int o = 16; o; o >>= 1) acc += __shfl_xor_sync(0xffffffffu, acc, o);
    if (lane == 0) shp[w] = acc;
    __syncthreads();

    if (w == 0) {
        float d = (lane < 8) ? shp[lane] : 0.f;
        d += __shfl_xor_sync(0xffffffffu, d, 1);   // lanes 0,2,4,6: row dots
        float invb = sh_invb;
        float s0 = __shfl_sync(0xffffffffu, d, 0) * g_rs[r0]     * invb;
        float s1 = __shfl_sync(0xffffffffu, d, 2) * g_rs[r0 + 1] * invb;
        float s2 = __shfl_sync(0xffffffffu, d, 4) * g_rs[r0 + 2] * invb;
        float s3 = __shfl_sync(0xffffffffu, d, 6) * g_rs[r0 + 3] * invb;
        if (lane < 4) {
            float sv = (lane == 0) ? s0 : (lane == 1) ? s1 : (lane == 2) ? s2 : s3;
            g_s[j * T_RES + r0 + lane] = sv;
        }
        if (lane < 16) {
            float cp = 0.f;
            if (lane <= j) {
                if (lane == j) {
                    cp = s0 * s0 + s1 * s1 + s2 * s2 + s3 * s3;
                } else {
                    const float* sk = g_s + (size_t)lane * T_RES + r0;
                    cp = sk[0] * s0 + sk[1] * s1 + sk[2] * s2 + sk[3] * s3;
                }
            }
            g_cpart[blockIdx.x * 16 + lane] = cp;
        }
    }
}

// ===== k_B1: u-quarter partials (4 t-quarters x 128 col-blocks, 64 cols) =====
__global__ void k_B1(int j) {
    __shared__ float s_sm[512];
    __shared__ float4 shA[NWC], shB[NWC];
    int tx = threadIdx.x;
    int tq = blockIdx.x >> 7;       // t-quarter
    int cb = blockIdx.x & 127;      // column block

    int tbase = tq * 512;
    if (tx < 512) s_sm[tx] = g_s[j * T_RES + tbase + tx] * g_rs[tbase + tx];
    __syncthreads();

    int g = tx & 7, s = tx >> 3;    // s in [0,64)
    const int4* Ri4 = (const int4*)g_Ri + (size_t)tbase * RI_STRIDE4;
    size_t cbase = (size_t)cb * 8 + g;
    float a[8];
    #pragma unroll
    for (int k = 0; k < 8; k++) a[k] = 0.f;
    #pragma unroll
    for (int it = 0; it < 8; it++) {
        int t = it * 64 + s;
        float sv = s_sm[t];
        int4 rv = __ldg(Ri4 + (size_t)t * RI_STRIDE4 + cbase);
        dq2(a[0], rv.x, sv, 0.f); dq2(a[1], rv.x, 0.f, sv);
        dq2(a[2], rv.y, sv, 0.f); dq2(a[3], rv.y, 0.f, sv);
        dq2(a[4], rv.z, sv, 0.f); dq2(a[5], rv.z, 0.f, sv);
        dq2(a[6], rv.w, sv, 0.f); dq2(a[7], rv.w, 0.f, sv);
    }
    shA[tx] = make_float4(a[0], a[1], a[2], a[3]);
    shB[tx] = make_float4(a[4], a[5], a[6], a[7]);
    #pragma unroll
    for (int off = 256; off >= 8; off >>= 1) {
        __syncthreads();
        if (tx < off) {
            float4 x = shA[tx], y = shA[tx + off];
            x.x += y.x; x.y += y.y; x.z += y.z; x.w += y.w; shA[tx] = x;
            x = shB[tx]; y = shB[tx + off];
            x.x += y.x; x.y += y.y; x.z += y.z; x.w += y.w; shB[tx] = x;
        }
    }
    __syncthreads();
    if (tx < 8) {
        float4 ua = shA[tx], ub = shB[tx];
        int c0 = cb * 64 + tx * 8;
        float* up = g_upart + tq * D_FEAT + c0;
        up[0] = ua.x; up[1] = ua.y; up[2] = ua.z; up[3] = ua.w;
        up[4] = ub.x; up[5] = ub.y; up[6] = ub.z; up[7] = ub.w;
    }
}

// ===== k_B2: combine quarters; reorth; Q[j]; new wf; nrm partials; alpha =====
__global__ void k_B2(int j, int last) {
    __shared__ float sh_c[ORDER];
    __shared__ float shn[4];
    int tx = threadIdx.x, lane = tx & 31, w = tx >> 5;

    {   // reduce c-partials (512 row-blocks x 16)
        int k = tx >> 4, i = tx & 15;
        float c = 0.f;
        #pragma unroll 8
        for (int m = 0; m < ROW_BLOCKS / 16; m++)
            c += g_cpart[(m * 16 + i) * 16 + k];
        #pragma unroll
        for (int o = 8; o; o >>= 1) c += __shfl_xor_sync(0xffffffffu, c, o);
        if (i == 0) sh_c[k] = c;
    }
    __syncthreads();

    if (blockIdx.x == 0 && tx == 0) g_alpha[j] = -sh_c[j];
    float invb = 1.0f / fmaxf(g_b[j], 1e-30f);
    int col = blockIdx.x * 128 + tx;

    if (last) {
        if (tx < 128) g_Q[(size_t)j * D_FEAT + col] = g_wf[col] * invb;
        return;
    }

    float nrm = 0.f;
    if (tx < 128) {
        float u = g_upart[col] + g_upart[D_FEAT + col]
                + g_upart[2 * D_FEAT + col] + g_upart[3 * D_FEAT + col];
        float qv = g_wf[col] * invb;
        g_Q[(size_t)j * D_FEAT + col] = qv;
        float wv = -u;
        for (int k = 0; k < j; k++)
            wv = fmaf(sh_c[k], g_Q[(size_t)k * D_FEAT + col], wv);
        wv = fmaf(sh_c[j], qv, wv);
        g_wf[col] = wv;
        nrm = wv * wv;
    }
    #pragma unroll
    for (int o = 16; o; o >>= 1) nrm += __shfl_xor_sync(0xffffffffu, nrm, o);
    if (lane == 0 && w < 4) shn[w] = nrm;
    __syncthreads();
    if (tx == 0) g_nrm2_part[blockIdx.x] = shn[0] + shn[1] + shn[2] + shn[3];
}

// == k_final: expm (inlined, warp0) + dtheta[p] = D[p].dir / (||D[p]||^2+REG) ==
__global__ void k_final(const float* __restrict__ Dm, float* __restrict__ out) {
    __shared__ float sh_a[8], sh_d[8];
    __shared__ float coeffs[ORDER];
    int p = blockIdx.x;
    int tx = threadIdx.x, lane = tx & 31, w = tx >> 5;

    if (w == 0) {  // exp(-T*DTAU) e0 via lane-parallel double Taylor
        double a = 0.0, bl = 0.0, bu = 0.0;
        if (lane < ORDER) a = (double)g_alpha[lane];
        if (lane >= 1 && lane < ORDER) bl = (double)g_b[lane];
        if (lane < ORDER - 1) bu = (double)g_b[lane + 1];
        double v = (lane == 0) ? 1.0 : 0.0, y = v;
        for (int k = 1; k <= 40; k++) {
            double vp = __shfl_up_sync(0xffffffffu, v, 1);
            double vn = __shfl_down_sync(0xffffffffu, v, 1);
            double t = a * v + bl * vp + bu * vn;
            v = t * (-DTAU / (double)k);
            y += v;
        }
        if (lane < ORDER) coeffs[lane] = (float)((double)g_b[0] * y);
    }
    __syncthreads();

    float cf[ORDER];
    #pragma unroll
    for (int l = 0; l < ORDER; l++) cf[l] = coeffs[l];
    const float* Dp = Dm + (size_t)p * D_FEAT;
    float acc = 0.f, den = 0.f;
    for (int d = tx; d < D_FEAT; d += NW) {
        float dir = 0.f;
        #pragma unroll
        for (int l = 0; l < ORDER; l++) dir = fmaf(cf[l], g_Q[(size_t)l * D_FEAT + d], dir);
        float dv = Dp[d];
        acc = fmaf(dv, dir, acc);
        den = fmaf(dv, dv, den);
    }
    #pragma unroll
    for (int o = 16; o; o >>= 1) {
        acc += __shfl_xor_sync(0xffffffffu, acc, o);
        den += __shfl_xor_sync(0xffffffffu, den, o);
    }
    if (lane == 0) { sh_a[w] = acc; sh_d[w] = den; }
    __syncthreads();
    if (tx == 0) {
        float A = 0.f, Dd = 0.f;
        #pragma unroll
        for (int i = 0; i < 8; i++) { A += sh_a[i]; Dd += sh_d[i]; }
        out[p] = A / (Dd + REG);
    }
}

// --------------------------------- launcher ----------------------------------
extern "C" void kernel_launch(void* const* d_in, const int* in_sizes, int n_in,
                              void* d_out, int out_size) {
    (void)out_size;
    const float* f = nullptr;
    const float* R = nullptr;
    const float* Dm = nullptr;
    for (int i = 0; i < n_in; i++) {
        if (in_sizes[i] == D_FEAT)               f  = (const float*)d_in[i];
        else if (in_sizes[i] == T_RES * D_FEAT)  R  = (const float*)d_in[i];
        else if (in_sizes[i] == ORDER * D_FEAT)  Dm = (const float*)d_in[i];
    }

    k_quant<<<256, NW>>>(R);
    k_row_f<<<256, NW>>>(f);
    k_prologue_col<<<128, NWC>>>(f);
    for (int j = 0; j < ORDER; j++) {
        k_A<<<ROW_BLOCKS, NW>>>(j, (j == 0) ? 128 : 64);
        if (j < ORDER - 1) k_B1<<<512, NWC>>>(j);
        k_B2<<<64, NW>>>(j, (j == ORDER - 1) ? 1 : 0);
    }
    k_final<<<ORDER, NW>>>(Dm, (float*)d_out);
}

// round 17
// speedup vs baseline: 1.5842x; 1.5842x over previous
#include <cuda_runtime.h>
#include <math.h>

#define D_FEAT 8192
#define T_RES  2048
#define ORDER  16
#define DTAU   0.08
#define REG    0.0001f
#define EPS_C  1e-15f

#define NBLK 148     // persistent blocks, 1 per SM (GB300 has 152 SMs)
#define NT   512
#define NCB  128     // col-epilogue blocks
#define CPB  64      // cols per col-block (128*64 = 8192)
#define MAXR 16      // max owned rows per block (actual 13..14)

// ---------------- device scratch (no allocations allowed) ----------------
__device__ short g_Ri[(size_t)T_RES * D_FEAT];   // int16 row-scaled R (32 MB)
__device__ float g_rs[T_RES];                    // dequant scale = rowmax/32767
__device__ float g_s[ORDER * T_RES];
__device__ float g_Q[ORDER * D_FEAT];
__device__ float g_wf[D_FEAT];
__device__ float g_upart[(size_t)NBLK * D_FEAT]; // per-block col partials
__device__ float g_ssf_part[NBLK];
__device__ float g_nrm2_part[NCB];
__device__ float g_cpart[NBLK * ORDER];
__device__ float g_b[ORDER + 1];
__device__ float g_alpha[ORDER];
__device__ float g_coeffs[ORDER];
__device__ unsigned g_bar_count;                 // zero-initialized
__device__ unsigned g_bar_gen;

// ---------------- grid barrier (all NBLK blocks resident) ----------------
__device__ __forceinline__ void grid_barrier() {
    __syncthreads();
    __threadfence();
    if (threadIdx.x == 0) {
        unsigned gen = *((volatile unsigned*)&g_bar_gen);
        if (atomicAdd(&g_bar_count, 1u) == NBLK - 1) {
            *((volatile unsigned*)&g_bar_count) = 0u;
            __threadfence();
            atomicAdd(&g_bar_gen, 1u);
        } else {
            while (*((volatile unsigned*)&g_bar_gen) == gen) { }
        }
        __threadfence();
    }
    __syncthreads();
}

// ---------------- block reduce + broadcast ----------------
__device__ __forceinline__ float blk_sum(float p, float* red, float* bc, int tx) {
    int lane = tx & 31, wid = tx >> 5;
    #pragma unroll
    for (int o = 16; o; o >>= 1) p += __shfl_xor_sync(0xffffffffu, p, o);
    if (lane == 0) red[wid] = p;
    __syncthreads();
    if (wid == 0) {
        float v = (lane < 16) ? red[lane] : 0.f;
        #pragma unroll
        for (int o = 8; o; o >>= 1) v += __shfl_xor_sync(0xffffffffu, v, o);
        if (lane == 0) *bc = v;
    }
    __syncthreads();
    return *bc;
}
__device__ __forceinline__ float blk_max(float p, float* red, float* bc, int tx) {
    int lane = tx & 31, wid = tx >> 5;
    #pragma unroll
    for (int o = 16; o; o >>= 1) p = fmaxf(p, __shfl_xor_sync(0xffffffffu, p, o));
    if (lane == 0) red[wid] = p;
    __syncthreads();
    if (wid == 0) {
        float v = (lane < 16) ? red[lane] : 0.f;
        #pragma unroll
        for (int o = 8; o; o >>= 1) v = fmaxf(v, __shfl_xor_sync(0xffffffffu, v, o));
        if (lane == 0) *bc = v;
    }
    __syncthreads();
    return *bc;
}

__device__ __forceinline__ float slo(int w) { return (float)((short)(w & 0xffff)); }
__device__ __forceinline__ float shi(int w) { return (float)(w >> 16); }

// dot of 16 int16 cols (2 int4) with 4 float4 weights
__device__ __forceinline__ float dot16(int4 ra, int4 rb,
                                       float4 w0, float4 w1, float4 w2, float4 w3) {
    float p = 0.f;
    p = fmaf(slo(ra.x), w0.x, p); p = fmaf(shi(ra.x), w0.y, p);
    p = fmaf(slo(ra.y), w0.z, p); p = fmaf(shi(ra.y), w0.w, p);
    p = fmaf(slo(ra.z), w1.x, p); p = fmaf(shi(ra.z), w1.y, p);
    p = fmaf(slo(ra.w), w1.z, p); p = fmaf(shi(ra.w), w1.w, p);
    p = fmaf(slo(rb.x), w2.x, p); p = fmaf(shi(rb.x), w2.y, p);
    p = fmaf(slo(rb.y), w2.z, p); p = fmaf(shi(rb.y), w2.w, p);
    p = fmaf(slo(rb.z), w3.x, p); p = fmaf(shi(rb.z), w3.y, p);
    p = fmaf(slo(rb.w), w3.z, p); p = fmaf(shi(rb.w), w3.w, p);
    return p;
}
// column accumulate: acc[c] += R~[r][col_c] * sp for this thread's 16 cols
__device__ __forceinline__ void accum16(float* a, int4 ra, int4 rb, float sp) {
    a[0]  = fmaf(slo(ra.x), sp, a[0]);  a[1]  = fmaf(shi(ra.x), sp, a[1]);
    a[2]  = fmaf(slo(ra.y), sp, a[2]);  a[3]  = fmaf(shi(ra.y), sp, a[3]);
    a[4]  = fmaf(slo(ra.z), sp, a[4]);  a[5]  = fmaf(shi(ra.z), sp, a[5]);
    a[6]  = fmaf(slo(ra.w), sp, a[6]);  a[7]  = fmaf(shi(ra.w), sp, a[7]);
    a[8]  = fmaf(slo(rb.x), sp, a[8]);  a[9]  = fmaf(shi(rb.x), sp, a[9]);
    a[10] = fmaf(slo(rb.y), sp, a[10]); a[11] = fmaf(shi(rb.y), sp, a[11]);
    a[12] = fmaf(slo(rb.z), sp, a[12]); a[13] = fmaf(shi(rb.z), sp, a[13]);
    a[14] = fmaf(slo(rb.w), sp, a[14]); a[15] = fmaf(shi(rb.w), sp, a[15]);
}
__device__ __forceinline__ void store_upart(const float* a, int b, int tx) {
    float4* up4 = (float4*)(g_upart + (size_t)b * D_FEAT);
    up4[2*tx]        = make_float4(a[0],  a[1],  a[2],  a[3]);
    up4[2*tx + 1]    = make_float4(a[4],  a[5],  a[6],  a[7]);
    up4[2*tx + 1024] = make_float4(a[8],  a[9],  a[10], a[11]);
    up4[2*tx + 1025] = make_float4(a[12], a[13], a[14], a[15]);
}

// ================================ the kernel ================================
__global__ void __launch_bounds__(NT, 1)
k_all(const float* __restrict__ Rg, const float* __restrict__ f,
      const float* __restrict__ Dm, float* __restrict__ out) {
    __shared__ float sh_red[16];
    __shared__ float sh_bc;
    __shared__ float sh_rs[MAXR];
    __shared__ float sh_sj[MAXR];
    __shared__ float sh_c[ORDER];
    __shared__ float sh_u[CPB];

    int tx = threadIdx.x, lane = tx & 31, wid = tx >> 5, b = blockIdx.x;
    int r0 = b * 13 + (b < 124 ? b : 124);       // row ownership: 124x14 + 24x13 = 2048
    int nr = (b < 124) ? 14 : 13;

    // ---------- P0: quantize owned rows (rowmax + int16 store) ----------
    for (int lr = 0; lr < nr; lr++) {
        const float4* Rr = (const float4*)(Rg + (size_t)(r0 + lr) * D_FEAT);
        float4 v0 = Rr[tx], v1 = Rr[tx + 512], v2 = Rr[tx + 1024], v3 = Rr[tx + 1536];
        float m = fmaxf(fmaxf(fmaxf(fabsf(v0.x), fabsf(v0.y)), fmaxf(fabsf(v0.z), fabsf(v0.w))),
                  fmaxf(fmaxf(fmaxf(fabsf(v1.x), fabsf(v1.y)), fmaxf(fabsf(v1.z), fabsf(v1.w))),
                  fmaxf(fmaxf(fmaxf(fabsf(v2.x), fabsf(v2.y)), fmaxf(fabsf(v2.z), fabsf(v2.w))),
                        fmaxf(fmaxf(fabsf(v3.x), fabsf(v3.y)), fmaxf(fabsf(v3.z), fabsf(v3.w))))));
        m = blk_max(m, sh_red, &sh_bc, tx);
        m = fmaxf(m, 1e-30f);
        if (tx == 0) g_rs[r0 + lr] = m / 32767.0f;
        float q = 32767.0f / m;
        short4* Or = (short4*)(g_Ri + (size_t)(r0 + lr) * D_FEAT);
        Or[tx] = make_short4((short)__float2int_rn(v0.x * q), (short)__float2int_rn(v0.y * q),
                             (short)__float2int_rn(v0.z * q), (short)__float2int_rn(v0.w * q));
        Or[tx + 512] = make_short4((short)__float2int_rn(v1.x * q), (short)__float2int_rn(v1.y * q),
                                   (short)__float2int_rn(v1.z * q), (short)__float2int_rn(v1.w * q));
        Or[tx + 1024] = make_short4((short)__float2int_rn(v2.x * q), (short)__float2int_rn(v2.y * q),
                                    (short)__float2int_rn(v2.z * q), (short)__float2int_rn(v2.w * q));
        Or[tx + 1536] = make_short4((short)__float2int_rn(v3.x * q), (short)__float2int_rn(v3.y * q),
                                    (short)__float2int_rn(v3.z * q), (short)__float2int_rn(v3.w * q));
    }
    grid_barrier();

    if (tx < nr) sh_rs[tx] = g_rs[r0 + tx];
    __syncthreads();

    // ---------- P1: sf = R~ f (fused row-dot + col-partials) ----------
    {
        const float4* f4 = (const float4*)f;
        float4 w0 = f4[2*tx], w1 = f4[2*tx+1], w2 = f4[1024+2*tx], w3 = f4[1024+2*tx+1];
        float acc[16];
        #pragma unroll
        for (int k = 0; k < 16; k++) acc[k] = 0.f;
        float ssfp = 0.f;
        for (int lr = 0; lr < nr; lr++) {
            const int4* row = (const int4*)(g_Ri + (size_t)(r0 + lr) * D_FEAT);
            int4 ra = row[tx], rb = row[tx + 512];
            float p = dot16(ra, rb, w0, w1, w2, w3);
            float dotr = blk_sum(p, sh_red, &sh_bc, tx);
            float sfr = dotr * sh_rs[lr];
            ssfp = fmaf(sfr, sfr, ssfp);
            accum16(acc, ra, rb, sfr * sh_rs[lr]);
        }
        if (tx == 0) g_ssf_part[b] = ssfp;
        store_upart(acc, b, tx);
    }
    grid_barrier();

    // ---------- P2: F = R~^T sf' + E f ; wf = F ; nrm partials ----------
    if (b < NCB) {
        const float4* f4 = (const float4*)f;
        float p = 0.f;
        for (int i = tx; i < D_FEAT / 4; i += NT) {
            float4 v = f4[i];
            p = fmaf(v.x, v.x, fmaf(v.y, v.y, fmaf(v.z, v.z, fmaf(v.w, v.w, p))));
        }
        float ff = blk_sum(p, sh_red, &sh_bc, tx);
        p = (tx < NBLK) ? g_ssf_part[tx] : 0.f;
        float ssf = blk_sum(p, sh_red, &sh_bc, tx);
        float E = -ssf / (ff + EPS_C);

        int colg = tx >> 3, sub = tx & 7, c0 = b * CPB;
        float u = 0.f;
        for (int bb = sub; bb < NBLK; bb += 8) u += g_upart[(size_t)bb * D_FEAT + c0 + colg];
        u += __shfl_down_sync(0xffffffffu, u, 4);
        u += __shfl_down_sync(0xffffffffu, u, 2);
        u += __shfl_down_sync(0xffffffffu, u, 1);
        if (sub == 0) sh_u[colg] = u;
        __syncthreads();
        float nrm = 0.f;
        if (tx < CPB) {
            int col = c0 + tx;
            float F = fmaf(E, f[col], sh_u[tx]);
            g_wf[col] = F;
            nrm = F * F;
        }
        float nt = blk_sum(nrm, sh_red, &sh_bc, tx);
        if (tx == 0) g_nrm2_part[b] = nt;
    }
    grid_barrier();

    // ================= Lanczos iterations =================
    float invb = 0.f;
    for (int j = 0; j < ORDER; j++) {
        // ---- phase A: b_j, s_j (row sweep) + col partials in ONE pass ----
        float p = (tx < NCB) ? g_nrm2_part[tx] : 0.f;
        float nrm = blk_sum(p, sh_red, &sh_bc, tx);
        float bj = sqrtf(nrm);
        invb = 1.0f / fmaxf(bj, 1e-30f);
        if (b == 0 && tx == 0) g_b[j] = bj;

        const float4* wf4 = (const float4*)g_wf;
        float4 w0 = wf4[2*tx], w1 = wf4[2*tx+1], w2 = wf4[1024+2*tx], w3 = wf4[1024+2*tx+1];
        float acc[16];
        #pragma unroll
        for (int k = 0; k < 16; k++) acc[k] = 0.f;

        for (int lr = 0; lr < nr; lr++) {
            const int4* row = (const int4*)(g_Ri + (size_t)(r0 + lr) * D_FEAT);
            int4 ra = row[tx], rb = row[tx + 512];
            float pd = dot16(ra, rb, w0, w1, w2, w3);
            float dotr = blk_sum(pd, sh_red, &sh_bc, tx);
            float sjr = dotr * sh_rs[lr] * invb;
            if (tx == 0) { g_s[j * T_RES + r0 + lr] = sjr; sh_sj[lr] = sjr; }
            if (j < ORDER - 1) accum16(acc, ra, rb, sjr * sh_rs[lr]);
        }
        __syncthreads();
        if (tx < 16) {
            float cp = 0.f;
            if (tx <= j) {
                if (tx == j) {
                    for (int lr = 0; lr < nr; lr++) cp = fmaf(sh_sj[lr], sh_sj[lr], cp);
                } else {
                    const float* sk = g_s + tx * T_RES + r0;
                    for (int lr = 0; lr < nr; lr++) cp = fmaf(sk[lr], sh_sj[lr], cp);
                }
            }
            g_cpart[b * 16 + tx] = cp;
        }
        if (j < ORDER - 1) store_upart(acc, b, tx);
        grid_barrier();

        // ---- phase C: c-reduce; u-reduce; reorth epilogue; new wf ----
        if (b < NCB) {
            if (wid <= j) {
                float c = 0.f;
                for (int bb = lane; bb < NBLK; bb += 32) c += g_cpart[bb * 16 + wid];
                #pragma unroll
                for (int o = 16; o; o >>= 1) c += __shfl_xor_sync(0xffffffffu, c, o);
                if (lane == 0) sh_c[wid] = c;
            }
            __syncthreads();
            if (b == 0 && tx == 0) g_alpha[j] = -sh_c[j];

            int colg = tx >> 3, sub = tx & 7, c0 = b * CPB;
            if (j < ORDER - 1) {
                float u = 0.f;
                for (int bb = sub; bb < NBLK; bb += 8) u += g_upart[(size_t)bb * D_FEAT + c0 + colg];
                u += __shfl_down_sync(0xffffffffu, u, 4);
                u += __shfl_down_sync(0xffffffffu, u, 2);
                u += __shfl_down_sync(0xffffffffu, u, 1);
                if (sub == 0) sh_u[colg] = u;
            }
            __syncthreads();
            float nrm2 = 0.f;
            if (tx < CPB) {
                int col = c0 + tx;
                float qv = g_wf[col] * invb;
                g_Q[j * D_FEAT + col] = qv;
                if (j < ORDER - 1) {
                    float wv = -sh_u[tx];
                    for (int k = 0; k < j; k++)
                        wv = fmaf(sh_c[k], g_Q[k * D_FEAT + col], wv);
                    wv = fmaf(sh_c[j], qv, wv);
                    g_wf[col] = wv;
                    nrm2 = wv * wv;
                }
            }
            if (j < ORDER - 1) {
                float nt = blk_sum(nrm2, sh_red, &sh_bc, tx);
                if (tx == 0) g_nrm2_part[b] = nt;
            }
        }
        grid_barrier();
    }

    // ---------- expm: coeffs = normF * exp(-T*DTAU) e0 ----------
    if (b == 0 && wid == 0) {
        double a = 0.0, bl = 0.0, bu = 0.0;
        if (lane < ORDER) a = (double)g_alpha[lane];
        if (lane >= 1 && lane < ORDER) bl = (double)g_b[lane];
        if (lane < ORDER - 1) bu = (double)g_b[lane + 1];
        double v = (lane == 0) ? 1.0 : 0.0, y = v;
        for (int k = 1; k <= 40; k++) {
            double vp = __shfl_up_sync(0xffffffffu, v, 1);
            double vn = __shfl_down_sync(0xffffffffu, v, 1);
            double t = a * v + bl * vp + bu * vn;
            v = t * (-DTAU / (double)k);
            y += v;
        }
        if (lane < ORDER) g_coeffs[lane] = (float)((double)g_b[0] * y);
    }
    grid_barrier();

    // ---------- final: dtheta[p] = D[p].dir / (||D[p]||^2 + REG) ----------
    if (b < ORDER) {
        float cf[ORDER];
        #pragma unroll
        for (int l = 0; l < ORDER; l++) cf[l] = g_coeffs[l];
        const float* Dp = Dm + (size_t)b * D_FEAT;
        float accd = 0.f, den = 0.f;
        for (int d = tx; d < D_FEAT; d += NT) {
            float dir = 0.f;
            #pragma unroll
            for (int l = 0; l < ORDER; l++) dir = fmaf(cf[l], g_Q[l * D_FEAT + d], dir);
            float dv = Dp[d];
            accd = fmaf(dv, dir, accd);
            den = fmaf(dv, dv, den);
        }
        accd = blk_sum(accd, sh_red, &sh_bc, tx);
        den  = blk_sum(den,  sh_red, &sh_bc, tx);
        if (tx == 0) out[b] = accd / (den + REG);
    }
}

// --------------------------------- launcher ----------------------------------
extern "C" void kernel_launch(void* const* d_in, const int* in_sizes, int n_in,
                              void* d_out, int out_size) {
    (void)out_size;
    const float* f = nullptr;
    const float* R = nullptr;
    const float* Dm = nullptr;
    for (int i = 0; i < n_in; i++) {
        if (in_sizes[i] == D_FEAT)               f  = (const float*)d_in[i];
        else if (in_sizes[i] == T_RES * D_FEAT)  R  = (const float*)d_in[i];
        else if (in_sizes[i] == ORDER * D_FEAT)  Dm = (const float*)d_in[i];
    }
    k_all<<<NBLK, NT>>>(R, f, Dm, (float*)d_out);
}